// round 12
// baseline (speedup 1.0000x reference)
#include <cuda_runtime.h>
#include <cstdint>

#define T_STEPS 4096
#define IN_SZ   1024
#define H       2048
#define MOD     256
#define NMOD    8
#define NCTA    128    // persistent CTAs for recurrence (< 148 SMs -> co-resident)
#define NREP    8      // value/counter replicas (reader CTA c uses replica c&7)

// ---------------------------------------------------------------------------
// Scratch (static device memory; no allocations allowed)
// ---------------------------------------------------------------------------
__device__ float g_U[(size_t)T_STEPS * H];   // 32MB: U[t-1][r] = x·W_ih^T + b_ih + b_hh

// Published h values, slice-spread:
//   addr(rep, slot, line, lane) = ((rep*2 + slot)*64 + line)*512 + lane
//   line = h_index/32 (0..63), lane = h_index%32. Line stride = 2KB so every
//   128B line gets distinct L2-hash bits (bits 11+). 2MB total.
#define GVAL_F4   (NREP * 2 * 64 * 512 / 4)          // 131072 float4s
__device__ float g_val[NREP * 2 * 64 * 512];

// Readiness counters: g_cnt2[rep*512 + j], 2KB replica stride. Counter
// (rep, j) reaches 128*epoch when all 128 CTAs have published module j.
__device__ unsigned g_cnt2[NREP * 512];

// ---------------------------------------------------------------------------
// memory-model primitives
// ---------------------------------------------------------------------------
__device__ __forceinline__ unsigned ld_acq_u32(const unsigned* p) {
    unsigned v;
    asm volatile("ld.acquire.gpu.global.u32 %0, [%1];" : "=r"(v) : "l"(p));
    return v;
}
__device__ __forceinline__ void st_rlx_f32(float* p, float v) {
    asm volatile("st.relaxed.gpu.global.f32 [%0], %1;" :: "l"(p), "f"(v));
}
__device__ __forceinline__ void red_rel_add(unsigned* p, unsigned v) {
    asm volatile("red.release.gpu.global.add.u32 [%0], %1;" :: "l"(p), "r"(v));
}

// ---------------------------------------------------------------------------
// Kernel 1: zero scratch state + input projection for active (step, module)
// pairs. grid = (512, 8). Blocks with blk = j*512+bx < 512 zero g_val
// (one float4 per thread, 512*256 = 131072 = exactly sizeof(g_val)/16);
// block 0 also zeroes the counters. Then CTA (bx, j) with bx < nb computes
// 8 consecutive active steps of module j: t = 2^j * (8*bx + k + 1), k=0..7.
// ---------------------------------------------------------------------------
__global__ __launch_bounds__(256) void input_gemm_kernel(
    const float* __restrict__ x, const float* __restrict__ W_ih,
    const float* __restrict__ b_ih, const float* __restrict__ b_hh)
{
    const int j   = blockIdx.y;
    const int bx  = blockIdx.x;
    const int tid = threadIdx.x;

    // ---- zero scratch (bounded to the real array size) ----
    {
        const int blk = j * 512 + bx;                       // 0..4095
        const int idx = blk * 256 + tid;
        if (idx < GVAL_F4)
            ((float4*)g_val)[idx] = make_float4(0.f, 0.f, 0.f, 0.f);
        if (blk == 0) {
            #pragma unroll
            for (int q = 0; q < NREP * 512 / 256; q++) g_cnt2[q * 256 + tid] = 0u;
        }
    }

    const int nb = (T_STEPS >> j) >> 3;
    if (bx >= nb) return;
    const int p = 1 << j;

    __shared__ float4 xs[8][IN_SZ / 4];                     // 32 KB
    #pragma unroll
    for (int k = 0; k < 8; k++) {
        int t = p * (bx * 8 + k + 1);                       // 1-indexed active step
        const float4* xr = (const float4*)(x + (size_t)(t - 1) * IN_SZ);
        xs[k][tid] = xr[tid];
    }
    __syncthreads();

    const int r = j * MOD + tid;
    const float4* wr = (const float4*)(W_ih + (size_t)r * IN_SZ);
    float acc[8] = {0.f, 0.f, 0.f, 0.f, 0.f, 0.f, 0.f, 0.f};
    #pragma unroll 2
    for (int q = 0; q < IN_SZ / 4; q++) {
        const float4 w = wr[q];
        #pragma unroll
        for (int k = 0; k < 8; k++) {
            const float4 xv = xs[k][q];
            acc[k] = fmaf(w.x, xv.x, fmaf(w.y, xv.y, fmaf(w.z, xv.z, fmaf(w.w, xv.w, acc[k]))));
        }
    }
    const float b = b_ih[r] + b_hh[r];
    #pragma unroll
    for (int k = 0; k < 8; k++) {
        int t = p * (bx * 8 + k + 1);
        g_U[(size_t)(t - 1) * H + r] = acc[k] + b;
    }
}

// ---------------------------------------------------------------------------
// Kernel 2: persistent recurrence. 128 CTAs x 256 threads, 1 CTA/SM.
// Warp w of CTA c owns rows r0 = w*256 + 2c, r1 = r0+1 (2 rows of module w).
// W_hh rows live in registers (128 f32/lane). Replica rep = c&7 is used for
// BOTH counter polls and value reads; writers publish to ALL 8 replicas with
// per-lane store->release chains (lane k owns replica k).
// ---------------------------------------------------------------------------
__global__ __launch_bounds__(256, 1) void recurrence_kernel(
    const float* __restrict__ W_hh, float* __restrict__ out)
{
    __shared__ __align__(16) float hsm[H];      // persistent staged h (8 KB)

    const int tid = threadIdx.x;
    const int w   = tid >> 5;
    const int l   = tid & 31;
    const int c   = blockIdx.x;                 // 0..127
    const int rep = c & (NREP - 1);
    const int r0  = w * MOD + 2 * c;
    const int r1  = r0 + 1;

    // This warp's two W_hh rows -> registers (128 f32/lane).
    float4 w0[16], w1[16];
    #pragma unroll
    for (int q = 0; q < 16; q++) {
        w0[q] = *(const float4*)(W_hh + (size_t)r0 * H + q * 128 + l * 4);
        w1[q] = *(const float4*)(W_hh + (size_t)r1 * H + q * 128 + l * 4);
    }

    // Writer-side constants (lanes 0..7 publish to replica = lane).
    const int wline = w * 8 + (c >> 4);         // line index of rows r0,r1
    const int wlane = (2 * c) & 31;             // lane slot within that line

    float hc0 = 0.f, hc1 = 0.f;                 // current h of owned rows (all lanes)
    const unsigned pmask = (1u << w) - 1u;      // warp active iff (t & pmask)==0
    int budget = 1 << 22;                       // hang guard (~4M polls, < 1s worst case)

    for (int t = 1; t <= T_STEPS; t++) {
        const unsigned tm = (unsigned)(t - 1);
        int nref = tm ? __ffs((int)tm) : NMOD;  // modules j < nref changed at step t-1
        if (nref > NMOD) nref = NMOD;
        const bool act = ((unsigned)t & pmask) == 0u;

        // Prefetch U for this step (warp-broadcast load, overlaps the polls).
        float2 uu = make_float2(0.f, 0.f);
        if (act) uu = *(const float2*)(g_U + (size_t)tm * H + r0);

        // ---- poll replica counters + refresh changed modules into hsm ----
        #pragma unroll
        for (int j = NMOD - 1; j >= 0; j--) {
            if (j < nref) {
                const unsigned expect = 128u * (tm >> j);
                const unsigned* cp = &g_cnt2[rep * 512 + j];
                unsigned cv = ld_acq_u32(cp);
                while (cv < expect) {
                    if (--budget < 0) break;    // hang guard
                    cv = ld_acq_u32(cp);
                }
                const int slot = (int)((tm >> j) & 1u);
                // warp w loads line j*8+w, lane l -> column j*256 + w*32 + l
                hsm[j * MOD + tid] = g_val[(((rep * 2 + slot) * 64) + j * 8 + w) * 512 + l];
            }
        }
        __syncthreads();

        // ---- recurrent dot for active warps: 8 independent FMA chains ----
        if (act) {
            float a0x = 0.f, a0y = 0.f, a0z = 0.f, a0w = 0.f;
            float a1x = 0.f, a1y = 0.f, a1z = 0.f, a1w = 0.f;
            #pragma unroll
            for (int q = 0; q < 16; q++) {
                const float4 hv = *(const float4*)(hsm + q * 128 + l * 4);
                a0x = fmaf(hv.x, w0[q].x, a0x);
                a0y = fmaf(hv.y, w0[q].y, a0y);
                a0z = fmaf(hv.z, w0[q].z, a0z);
                a0w = fmaf(hv.w, w0[q].w, a0w);
                a1x = fmaf(hv.x, w1[q].x, a1x);
                a1y = fmaf(hv.y, w1[q].y, a1y);
                a1z = fmaf(hv.z, w1[q].z, a1z);
                a1w = fmaf(hv.w, w1[q].w, a1w);
            }
            float a0 = (a0x + a0y) + (a0z + a0w);
            float a1 = (a1x + a1y) + (a1z + a1w);
            #pragma unroll
            for (int off = 16; off >= 1; off >>= 1) {       // full butterfly: sums in ALL lanes
                a0 += __shfl_xor_sync(0xffffffffu, a0, off);
                a1 += __shfl_xor_sync(0xffffffffu, a1, off);
            }
            hc0 = tanhf(uu.x + a0);
            hc1 = tanhf(uu.y + a1);
            // Publish: lane k owns replica k (store both values, then release
            // that replica's counter — single-lane acq/rel chain with readers).
            if (l < NREP) {
                const int slot = (t >> w) & 1;
                float* vp = &g_val[(((l * 2 + slot) * 64) + wline) * 512 + wlane];
                st_rlx_f32(vp,     hc0);
                st_rlx_f32(vp + 1, hc1);
                red_rel_add(&g_cnt2[l * 512 + w], 1u);
            }
        }
        // ---- output (every warp, every step: fresh or carried value) ----
        if (l == 0) {
            *(float2*)(out + (size_t)tm * H + r0) = make_float2(hc0, hc1);
        }
        __syncthreads();                        // dot done before next refresh writes hsm
    }
}

// ---------------------------------------------------------------------------
extern "C" void kernel_launch(void* const* d_in, const int* in_sizes, int n_in,
                              void* d_out, int out_size)
{
    const float* x    = (const float*)d_in[0];
    const float* W_ih = (const float*)d_in[1];
    const float* W_hh = (const float*)d_in[2];
    const float* b_ih = (const float*)d_in[3];
    const float* b_hh = (const float*)d_in[4];
    float* out = (float*)d_out;

    input_gemm_kernel<<<dim3(512, NMOD), 256>>>(x, W_ih, b_ih, b_hh);
    recurrence_kernel<<<NCTA, 256>>>(W_hh, out);
}